// round 2
// baseline (speedup 1.0000x reference)
#include <cuda_runtime.h>

#define N_NODES   200000
#define N_EDGES   600000
#define NODE_SIZE 256
#define EDGE_SIZE 64
#define OUT       256
#define KTOT      576          // 256 self + 256 node_sum + 64 edge_sum
#define BUCKET    40000
#define NDEG      5
#define BM        64
#define BK        16
#define NBLK      (N_NODES / BM)   // 3125

// ---------------- scratch (device globals; no runtime allocation) ----------
__device__ float g_acts[(size_t)N_NODES * OUT];     // ~205 MB
__device__ float g_BT[NDEG * KTOT * OUT];           // combined transposed weights
__device__ float g_sum[OUT];
__device__ float g_sq[OUT];
__device__ float g_scale[OUT];
__device__ float g_shift[OUT];

// ---------------- packed f32x2 helpers -------------------------------------
__device__ __forceinline__ unsigned long long pk2(float x) {
    unsigned long long r;
    asm("mov.b64 %0, {%1, %1};" : "=l"(r) : "f"(x));
    return r;
}
__device__ __forceinline__ void fma2(unsigned long long& d,
                                     unsigned long long a,
                                     unsigned long long b) {
    asm("fma.rn.f32x2 %0, %1, %2, %0;" : "+l"(d) : "l"(a), "l"(b));
}
__device__ __forceinline__ float2 upk2(unsigned long long v) {
    float2 f;
    asm("mov.b64 {%0, %1}, %2;" : "=f"(f.x), "=f"(f.y) : "l"(v));
    return f;
}

// ---------------- kernel 0: build combined transposed weight ---------------
// BT[d][k][o] = (k < 256) ? W_self[o][k] : W_deg[d][o][k-256]
__global__ void build_bt_kernel(const float* __restrict__ W_self,
                                const float* __restrict__ W_deg) {
    int dk = blockIdx.x;            // 0 .. NDEG*KTOT-1
    int d = dk / KTOT;
    int k = dk - d * KTOT;
    int o = threadIdx.x;            // 0..255
    float v;
    if (k < NODE_SIZE) v = W_self[o * NODE_SIZE + k];
    else               v = W_deg[((size_t)(d * OUT + o)) * (NODE_SIZE + EDGE_SIZE) + (k - NODE_SIZE)];
    g_BT[(size_t)dk * OUT + o] = v;
}

// ---------------- kernel 1: zero stats --------------------------------------
__global__ void zero_stats_kernel() {
    int t = threadIdx.x;
    if (t < OUT) { g_sum[t] = 0.f; g_sq[t] = 0.f; }
}

// ---------------- kernel 2: fused gather + GEMM + stat partials -------------
struct NbrPtrs {
    const int* nn[NDEG];
    const int* en[NDEG];
};

__global__ __launch_bounds__(256, 2)
void gemm_kernel(const float* __restrict__ node_repr,
                 const float* __restrict__ edge_repr,
                 NbrPtrs p,
                 const float* __restrict__ bias) {
    __shared__ float As[BK][BM];        // 4 KB, k-major
    __shared__ float Bs[BK][OUT];       // 16 KB, k-major (reused for reductions)
    __shared__ int   s_nn[BM][NDEG];
    __shared__ int   s_en[BM][NDEG];

    const int tid    = threadIdx.x;
    const int row0   = blockIdx.x * BM;
    const int bucket = row0 / BUCKET;           // whole block in one bucket
    const int deg    = bucket + 1;
    const int li0    = row0 - bucket * BUCKET;

    // neighbor indices for this tile
    {
        const int* nn = p.nn[bucket];
        const int* en = p.en[bucket];
        for (int t = tid; t < BM * deg; t += 256) {
            int r = t / deg, j = t - r * deg;
            s_nn[r][j] = nn[(li0 + r) * deg + j];
            s_en[r][j] = en[(li0 + r) * deg + j];
        }
    }

    unsigned long long acc[4][8];
    #pragma unroll
    for (int i = 0; i < 4; ++i)
        #pragma unroll
        for (int j = 0; j < 8; ++j) acc[i][j] = 0ULL;

    const int kc = tid >> 6;          // 0..3  (A loader role)
    const int rr = tid & 63;          // row   (A loader role)
    const int ty = tid >> 4;          // 0..15 row group
    const int tx = tid & 15;          // 0..15 col group

    const float4* btile = (const float4*)(g_BT + (size_t)bucket * KTOT * OUT);

    __syncthreads();   // s_nn / s_en visible

    for (int kt = 0; kt < KTOT / BK; ++kt) {
        const int k0 = kt * BK;

        // ---- stage global -> registers (overlaps prior compute drain) ----
        float4 breg[4];
        {
            const float4* bsrc = btile + (size_t)k0 * (OUT / 4);
            #pragma unroll
            for (int j = 0; j < 4; ++j) breg[j] = bsrc[tid + j * 256];
        }
        float4 v;
        if (k0 < NODE_SIZE) {
            v = *(const float4*)(node_repr + (size_t)(row0 + rr) * NODE_SIZE + k0 + kc * 4);
        } else if (k0 < 2 * NODE_SIZE) {
            v = make_float4(0.f, 0.f, 0.f, 0.f);
            const int kk = k0 - NODE_SIZE + kc * 4;
            for (int j = 0; j < deg; ++j) {
                const float4 w = *(const float4*)(node_repr + (size_t)s_nn[rr][j] * NODE_SIZE + kk);
                v.x += w.x; v.y += w.y; v.z += w.z; v.w += w.w;
            }
        } else {
            v = make_float4(0.f, 0.f, 0.f, 0.f);
            const int kk = k0 - 2 * NODE_SIZE + kc * 4;
            for (int j = 0; j < deg; ++j) {
                const float4 w = *(const float4*)(edge_repr + (size_t)s_en[rr][j] * EDGE_SIZE + kk);
                v.x += w.x; v.y += w.y; v.z += w.z; v.w += w.w;
            }
        }

        __syncthreads();   // previous tile fully consumed

        // ---- commit to smem ----
        {
            float4* bdst = (float4*)Bs;
            #pragma unroll
            for (int j = 0; j < 4; ++j) bdst[tid + j * 256] = breg[j];
        }
        As[kc * 4 + 0][rr] = v.x;
        As[kc * 4 + 1][rr] = v.y;
        As[kc * 4 + 2][rr] = v.z;
        As[kc * 4 + 3][rr] = v.w;

        __syncthreads();

        // ---- compute 16 k-steps ----
        #pragma unroll
        for (int k = 0; k < BK; ++k) {
            const float4 a4 = *(const float4*)&As[k][ty * 4];
            const unsigned long long a0 = pk2(a4.x);
            const unsigned long long a1 = pk2(a4.y);
            const unsigned long long a2 = pk2(a4.z);
            const unsigned long long a3 = pk2(a4.w);
            const unsigned long long* bp =
                (const unsigned long long*)&Bs[k][tx * 16];
            #pragma unroll
            for (int pz = 0; pz < 8; ++pz) {
                const unsigned long long b = bp[pz];
                fma2(acc[0][pz], a0, b);
                fma2(acc[1][pz], a1, b);
                fma2(acc[2][pz], a2, b);
                fma2(acc[3][pz], a3, b);
            }
        }
    }

    // ---- epilogue: bias, store acts, column sum / sumsq partials ----
    float vals[4][16];
    #pragma unroll
    for (int i = 0; i < 4; ++i)
        #pragma unroll
        for (int pz = 0; pz < 8; ++pz) {
            float2 f = upk2(acc[i][pz]);
            vals[i][2 * pz]     = f.x;
            vals[i][2 * pz + 1] = f.y;
        }

    // bias
    {
        #pragma unroll
        for (int q = 0; q < 4; ++q) {
            const float4 bb = *(const float4*)(bias + tx * 16 + q * 4);
            #pragma unroll
            for (int i = 0; i < 4; ++i) {
                vals[i][q * 4 + 0] += bb.x;
                vals[i][q * 4 + 1] += bb.y;
                vals[i][q * 4 + 2] += bb.z;
                vals[i][q * 4 + 3] += bb.w;
            }
        }
    }

    // store acts
    #pragma unroll
    for (int i = 0; i < 4; ++i) {
        float* dst = g_acts + (size_t)(row0 + ty * 4 + i) * OUT + tx * 16;
        #pragma unroll
        for (int q = 0; q < 4; ++q)
            *(float4*)(dst + q * 4) = make_float4(vals[i][q * 4 + 0], vals[i][q * 4 + 1],
                                                  vals[i][q * 4 + 2], vals[i][q * 4 + 3]);
    }

    // per-column partials
    float s[16], q[16];
    #pragma unroll
    for (int c = 0; c < 16; ++c) {
        float ss = 0.f, qq = 0.f;
        #pragma unroll
        for (int i = 0; i < 4; ++i) { ss += vals[i][c]; qq += vals[i][c] * vals[i][c]; }
        s[c] = ss; q[c] = qq;
    }

    float* red = &Bs[0][0];    // 4096 floats scratch
    __syncthreads();           // done reading Bs as B tile
    #pragma unroll
    for (int c = 0; c < 16; ++c) red[ty * 256 + tx * 16 + c] = s[c];
    __syncthreads();
    {
        float tot = 0.f;
        #pragma unroll
        for (int y = 0; y < 16; ++y) tot += red[y * 256 + tid];
        atomicAdd(&g_sum[tid], tot);
    }
    __syncthreads();
    #pragma unroll
    for (int c = 0; c < 16; ++c) red[ty * 256 + tx * 16 + c] = q[c];
    __syncthreads();
    {
        float tot = 0.f;
        #pragma unroll
        for (int y = 0; y < 16; ++y) tot += red[y * 256 + tid];
        atomicAdd(&g_sq[tid], tot);
    }
}

// ---------------- kernel 3: finalize BN stats -------------------------------
__global__ void finalize_stats_kernel() {
    int c = threadIdx.x;
    float m   = g_sum[c] * (1.0f / N_NODES);
    float var = g_sq[c] * (1.0f / N_NODES) - m * m;
    float inv = rsqrtf(var + 1e-5f);
    g_scale[c] = inv;
    g_shift[c] = -m * inv;
}

// ---------------- kernel 4: normalize + relu --------------------------------
__global__ __launch_bounds__(256)
void norm_relu_kernel(float* __restrict__ out) {
    const size_t idx = (size_t)blockIdx.x * blockDim.x + threadIdx.x;  // float4 index
    const size_t total4 = (size_t)N_NODES * OUT / 4;
    if (idx >= total4) return;
    const int c4 = (int)(idx & (OUT / 4 - 1));
    const float4 v  = ((const float4*)g_acts)[idx];
    const float4 sc = ((const float4*)g_scale)[c4];
    const float4 sh = ((const float4*)g_shift)[c4];
    float4 r;
    r.x = fmaxf(0.f, v.x * sc.x + sh.x);
    r.y = fmaxf(0.f, v.y * sc.y + sh.y);
    r.z = fmaxf(0.f, v.z * sc.z + sh.z);
    r.w = fmaxf(0.f, v.w * sc.w + sh.w);
    ((float4*)out)[idx] = r;
}

// ---------------- launch -----------------------------------------------------
extern "C" void kernel_launch(void* const* d_in, const int* in_sizes, int n_in,
                              void* d_out, int out_size) {
    const float* node_repr = (const float*)d_in[0];
    const float* edge_repr = (const float*)d_in[1];
    NbrPtrs p;
    // setup_inputs() dict order is INTERLEAVED per degree:
    //   d_in[2]=node_nbr_1, d_in[3]=edge_nbr_1, d_in[4]=node_nbr_2, ...
    for (int d = 0; d < NDEG; ++d) {
        p.nn[d] = (const int*)d_in[2 + 2 * d];
        p.en[d] = (const int*)d_in[3 + 2 * d];
    }
    const float* W_self = (const float*)d_in[12];
    const float* W_deg  = (const float*)d_in[13];
    const float* bias   = (const float*)d_in[14];
    float* out = (float*)d_out;

    build_bt_kernel<<<NDEG * KTOT, 256>>>(W_self, W_deg);
    zero_stats_kernel<<<1, 256>>>();
    gemm_kernel<<<NBLK, 256>>>(node_repr, edge_repr, p, bias);
    finalize_stats_kernel<<<1, 256>>>();
    const int total4 = N_NODES * OUT / 4;
    norm_relu_kernel<<<(total4 + 255) / 256, 256>>>(out);
}

// round 4
// speedup vs baseline: 6.4505x; 6.4505x over previous
#include <cuda_runtime.h>
#include <cuda_fp16.h>

#define N_NODES   200000
#define N_EDGES   600000
#define NODE_SIZE 256
#define EDGE_SIZE 64
#define OUT       256
#define KTOT      576
#define BUCKET    40000
#define NDEG      5
#define CHUNKS    9                 // 9 x 64-k chunks
#define TILES_PB  313               // ceil(40000/128)
#define NTILES    (NDEG * TILES_PB) // 1565
#define THREADS   512

// ---- device scratch --------------------------------------------------------
__device__ float          g_acts[(size_t)N_NODES * OUT];
__device__ float          g_sum[OUT];
__device__ float          g_sq[OUT];
__device__ float          g_scale[OUT];
__device__ float          g_shift[OUT];
// pre-swizzled fp16 weights: [bucket*9+chunk] blobs of 256 rows x 128B
__device__ unsigned short g_B[45 * 16384];

// ---- SMEM layout (dynamic) ---------------------------------------------------
// buf s at s*49152:  A 128x128B (16384) ; B 256x128B at +16384 (32768)
// 98304:  s_nn (128*5*4=2560)
// 100864: s_en (2560)
// 103424: s_sum (1024) ; 104448: s_sq (1024)
#define SM_BUF    49152
#define SM_BOFF   16384
#define SM_NN     98304
#define SM_EN     100864
#define SM_SUM    103424
#define SM_SQ     104448
#define SM_BYTES  105472

static __device__ __forceinline__ void mma16816(float* d, const unsigned* a,
                                                const unsigned* b) {
    asm volatile(
        "mma.sync.aligned.m16n8k16.row.col.f32.f16.f16.f32 "
        "{%0,%1,%2,%3}, {%4,%5,%6,%7}, {%8,%9}, {%0,%1,%2,%3};"
        : "+f"(d[0]), "+f"(d[1]), "+f"(d[2]), "+f"(d[3])
        : "r"(a[0]), "r"(a[1]), "r"(a[2]), "r"(a[3]), "r"(b[0]), "r"(b[1]));
}

// ---- kernel 0: build pre-swizzled fp16 weight blobs --------------------------
// blob(bucket,c): element (n,k) at half-index n*64 + ((k>>3)^(n&7))*8 + (k&7)
__global__ void build_b_kernel(const float* __restrict__ W_self,
                               const float* __restrict__ W_deg) {
    const int bc = blockIdx.x;              // bucket*9 + chunk
    const int d = bc / CHUNKS, c = bc - d * CHUNKS;
    const int n = threadIdx.x;              // 0..255
    unsigned short* blob = g_B + (size_t)bc * 16384 + n * 64;
    const unsigned sx = n & 7;
    for (int k = 0; k < 64; ++k) {
        const int kg = c * 64 + k;
        float w;
        if (kg < NODE_SIZE)
            w = W_self[n * NODE_SIZE + kg];
        else
            w = W_deg[((size_t)(d * OUT + n)) * (NODE_SIZE + EDGE_SIZE) + (kg - NODE_SIZE)];
        blob[(((unsigned)(k >> 3)) ^ sx) * 8 + (k & 7)] = __half_as_ushort(__float2half_rn(w));
    }
}

// ---- kernel 1: zero stats -----------------------------------------------------
__global__ void zero_stats_kernel() {
    int t = threadIdx.x;
    if (t < OUT) { g_sum[t] = 0.f; g_sq[t] = 0.f; }
}

// ---- kernel 2: fused gather + HMMA GEMM + stats -------------------------------
struct NbrPtrs { const int* nn[NDEG]; const int* en[NDEG]; };

// gather 16 fp32 values of chunk cc for this thread into s[4] (float4)
static __device__ __forceinline__ void gatherA(
    int cc, int row, int q, bool live, int row0, int deg,
    const float* __restrict__ node_repr, const float* __restrict__ edge_repr,
    const int* s_nn, const int* s_en, float4* s) {
    s[0] = s[1] = s[2] = s[3] = make_float4(0.f, 0.f, 0.f, 0.f);
    if (!live) return;
    if (cc < 4) {
        const float4* p = (const float4*)(node_repr + (size_t)(row0 + row) * NODE_SIZE + cc * 64 + q * 16);
        #pragma unroll
        for (int i = 0; i < 4; ++i) s[i] = p[i];
    } else if (cc < 8) {
        const int kk = (cc - 4) * 64 + q * 16;
        for (int j = 0; j < deg; ++j) {
            const float4* p = (const float4*)(node_repr + (size_t)s_nn[row * NDEG + j] * NODE_SIZE + kk);
            #pragma unroll
            for (int i = 0; i < 4; ++i) {
                float4 w = p[i];
                s[i].x += w.x; s[i].y += w.y; s[i].z += w.z; s[i].w += w.w;
            }
        }
    } else {
        for (int j = 0; j < deg; ++j) {
            const float4* p = (const float4*)(edge_repr + (size_t)s_en[row * NDEG + j] * EDGE_SIZE + q * 16);
            #pragma unroll
            for (int i = 0; i < 4; ++i) {
                float4 w = p[i];
                s[i].x += w.x; s[i].y += w.y; s[i].z += w.z; s[i].w += w.w;
            }
        }
    }
}

// convert 16 fp32 -> fp16 and store 2x16B into swizzled A tile
static __device__ __forceinline__ void cvtStsA(char* bufA, int row, int q, const float4* s) {
    unsigned h[8];
    #pragma unroll
    for (int i = 0; i < 4; ++i) {
        __half2 p0 = __floats2half2_rn(((const float*)&s[i])[0], ((const float*)&s[i])[1]);
        __half2 p1 = __floats2half2_rn(((const float*)&s[i])[2], ((const float*)&s[i])[3]);
        h[2 * i]     = *(unsigned*)&p0;
        h[2 * i + 1] = *(unsigned*)&p1;
    }
    const unsigned sx = row & 7;
    unsigned off0 = row * 128 + ((((unsigned)(q * 2))     ^ sx) << 4);
    unsigned off1 = row * 128 + ((((unsigned)(q * 2 + 1)) ^ sx) << 4);
    *(uint4*)(bufA + off0) = make_uint4(h[0], h[1], h[2], h[3]);
    *(uint4*)(bufA + off1) = make_uint4(h[4], h[5], h[6], h[7]);
}

static __device__ __forceinline__ void loadBregs(int bucket, int cc, int tid, uint4* br) {
    const uint4* src = (const uint4*)(g_B + (size_t)(bucket * CHUNKS + cc) * 16384);
    #pragma unroll
    for (int i = 0; i < 4; ++i) br[i] = src[tid + i * 512];
}
static __device__ __forceinline__ void stsB(char* bufB, int tid, const uint4* br) {
    uint4* dst = (uint4*)bufB;
    #pragma unroll
    for (int i = 0; i < 4; ++i) dst[tid + i * 512] = br[i];
}

__global__ __launch_bounds__(THREADS, 1)
void tile_kernel(const float* __restrict__ node_repr,
                 const float* __restrict__ edge_repr,
                 NbrPtrs p) {
    extern __shared__ char smem[];
    const int tid    = threadIdx.x;
    const int bid    = blockIdx.x;
    const int bucket = bid / TILES_PB;
    const int tile   = bid - bucket * TILES_PB;
    const int deg    = bucket + 1;
    const int li0    = tile * 128;
    const int row0   = bucket * BUCKET + li0;
    const int valid  = (BUCKET - li0) < 128 ? (BUCKET - li0) : 128;

    int* s_nn = (int*)(smem + SM_NN);
    int* s_en = (int*)(smem + SM_EN);
    float* s_sum = (float*)(smem + SM_SUM);
    float* s_sq  = (float*)(smem + SM_SQ);

    if (tid < 256) { s_sum[tid] = 0.f; s_sq[tid] = 0.f; }

    {   // neighbor indices
        const int* nn = p.nn[bucket];
        const int* en = p.en[bucket];
        for (int i = tid; i < valid * deg; i += THREADS) {
            int r = i / deg, j = i - r * deg;
            s_nn[r * NDEG + j] = nn[(li0 + r) * deg + j];
            s_en[r * NDEG + j] = en[(li0 + r) * deg + j];
        }
    }
    __syncthreads();

    const int row = tid >> 2;          // staging row 0..127
    const int q   = tid & 3;           // staging k-quad
    const bool live = row < valid;

    // stage chunk 0 into buf 0
    {
        float4 ar[4]; uint4 br[4];
        gatherA(0, row, q, live, row0, deg, node_repr, edge_repr, s_nn, s_en, ar);
        loadBregs(bucket, 0, tid, br);
        cvtStsA(smem, row, q, ar);
        stsB(smem + SM_BOFF, tid, br);
    }
    __syncthreads();

    // warp/lane geometry for MMA
    const int wid  = tid >> 5, lane = tid & 31;
    const int wr   = wid & 3,  wc   = wid >> 2;
    const unsigned sx = (lane >> 2) & 7;
    const unsigned qa = (lane & 3) * 4;
    const int m1 = wr * 32 + (lane >> 2);       // A fragment base row
    const int nb = wc * 64 + (lane >> 2);       // B fragment base row

    float acc[2][8][4];
    #pragma unroll
    for (int mt = 0; mt < 2; ++mt)
        #pragma unroll
        for (int nt = 0; nt < 8; ++nt)
            #pragma unroll
            for (int i = 0; i < 4; ++i) acc[mt][nt][i] = 0.f;

    for (int c = 0; c < CHUNKS; ++c) {
        const int nxt = c + 1;
        float4 ar[4]; uint4 br[4];
        if (nxt < CHUNKS) {   // prefetch next chunk (LDGs fly during MMA)
            gatherA(nxt, row, q, live, row0, deg, node_repr, edge_repr, s_nn, s_en, ar);
            loadBregs(bucket, nxt, tid, br);
        }

        // ---- MMA on buffer c&1 ----
        {
            const char* bufA = smem + (c & 1) * SM_BUF;
            const char* bufB = bufA + SM_BOFF;
            #pragma unroll
            for (int ks = 0; ks < 4; ++ks) {
                const unsigned c0 = 2 * ks;
                const unsigned off0 = (((c0)     ^ sx) << 4) + qa;
                const unsigned off1 = (((c0 + 1) ^ sx) << 4) + qa;
                unsigned a[2][4];
                #pragma unroll
                for (int mt = 0; mt < 2; ++mt) {
                    const char* base = bufA + (m1 + mt * 16) * 128;
                    a[mt][0] = *(const unsigned*)(base + off0);
                    a[mt][1] = *(const unsigned*)(base + 8 * 128 + off0);
                    a[mt][2] = *(const unsigned*)(base + off1);
                    a[mt][3] = *(const unsigned*)(base + 8 * 128 + off1);
                }
                unsigned b[8][2];
                #pragma unroll
                for (int nt = 0; nt < 8; ++nt) {
                    const char* base = bufB + (nb + nt * 8) * 128;
                    b[nt][0] = *(const unsigned*)(base + off0);
                    b[nt][1] = *(const unsigned*)(base + off1);
                }
                #pragma unroll
                for (int mt = 0; mt < 2; ++mt)
                    #pragma unroll
                    for (int nt = 0; nt < 8; ++nt)
                        mma16816(acc[mt][nt], a[mt], b[nt]);
            }
        }

        if (nxt < CHUNKS) {   // commit next chunk to other buffer
            char* bufA = smem + (nxt & 1) * SM_BUF;
            cvtStsA(bufA, row, q, ar);
            stsB(bufA + SM_BOFF, tid, br);
        }
        __syncthreads();
    }

    // ---- epilogue: store acts, per-column stats ----
    {
        #pragma unroll
        for (int mt = 0; mt < 2; ++mt) {
            const int r0 = wr * 32 + mt * 16 + (lane >> 2);
            #pragma unroll
            for (int nt = 0; nt < 8; ++nt) {
                const int n0 = wc * 64 + nt * 8 + (lane & 3) * 2;
                if (r0 < valid)
                    *(float2*)(g_acts + (size_t)(row0 + r0) * OUT + n0) =
                        make_float2(acc[mt][nt][0], acc[mt][nt][1]);
                if (r0 + 8 < valid)
                    *(float2*)(g_acts + (size_t)(row0 + r0 + 8) * OUT + n0) =
                        make_float2(acc[mt][nt][2], acc[mt][nt][3]);
            }
        }
        // column partial sums over this warp's 32 rows (dead rows contribute 0)
        #pragma unroll
        for (int nt = 0; nt < 8; ++nt) {
            #pragma unroll
            for (int h = 0; h < 2; ++h) {
                float s = acc[0][nt][h] + acc[0][nt][2 + h] +
                          acc[1][nt][h] + acc[1][nt][2 + h];
                float qq = acc[0][nt][h] * acc[0][nt][h] + acc[0][nt][2 + h] * acc[0][nt][2 + h] +
                           acc[1][nt][h] * acc[1][nt][h] + acc[1][nt][2 + h] * acc[1][nt][2 + h];
                #pragma unroll
                for (int d = 4; d < 32; d <<= 1) {
                    s  += __shfl_xor_sync(0xffffffffu, s, d);
                    qq += __shfl_xor_sync(0xffffffffu, qq, d);
                }
                if (lane < 4) {
                    const int col = wc * 64 + nt * 8 + lane * 2 + h;
                    atomicAdd(&s_sum[col], s);
                    atomicAdd(&s_sq[col], qq);
                }
            }
        }
    }
    __syncthreads();
    if (tid < 256) {
        atomicAdd(&g_sum[tid], s_sum[tid]);
        atomicAdd(&g_sq[tid],  s_sq[tid]);
    }
}

// ---- kernel 3: finalize BN stats ----------------------------------------------
__global__ void finalize_stats_kernel() {
    int c = threadIdx.x;
    float m   = g_sum[c] * (1.0f / N_NODES);
    float var = g_sq[c] * (1.0f / N_NODES) - m * m;
    float inv = rsqrtf(var + 1e-5f);
    g_scale[c] = inv;
    g_shift[c] = -m * inv;
}

// ---- kernel 4: normalize + relu --------------------------------------------------
__global__ __launch_bounds__(256)
void norm_relu_kernel(float* __restrict__ out) {
    const size_t idx = (size_t)blockIdx.x * blockDim.x + threadIdx.x;
    const size_t total4 = (size_t)N_NODES * OUT / 4;
    if (idx >= total4) return;
    const int c4 = (int)(idx & (OUT / 4 - 1));
    const float4 v  = ((const float4*)g_acts)[idx];
    const float4 sc = ((const float4*)g_scale)[c4];
    const float4 sh = ((const float4*)g_shift)[c4];
    float4 r;
    r.x = fmaxf(0.f, v.x * sc.x + sh.x);
    r.y = fmaxf(0.f, v.y * sc.y + sh.y);
    r.z = fmaxf(0.f, v.z * sc.z + sh.z);
    r.w = fmaxf(0.f, v.w * sc.w + sh.w);
    ((float4*)out)[idx] = r;
}

// ---- launch -----------------------------------------------------------------------
extern "C" void kernel_launch(void* const* d_in, const int* in_sizes, int n_in,
                              void* d_out, int out_size) {
    const float* node_repr = (const float*)d_in[0];
    const float* edge_repr = (const float*)d_in[1];
    NbrPtrs p;
    // inputs interleaved: d_in[2]=node_nbr_1, d_in[3]=edge_nbr_1, ...
    for (int d = 0; d < NDEG; ++d) {
        p.nn[d] = (const int*)d_in[2 + 2 * d];
        p.en[d] = (const int*)d_in[3 + 2 * d];
    }
    const float* W_self = (const float*)d_in[12];
    const float* W_deg  = (const float*)d_in[13];
    float* out = (float*)d_out;

    static bool attr_done = false;
    if (!attr_done) {
        cudaFuncSetAttribute(tile_kernel, cudaFuncAttributeMaxDynamicSharedMemorySize, SM_BYTES);
        attr_done = true;
    }

    build_b_kernel<<<NDEG * CHUNKS, 256>>>(W_self, W_deg);
    zero_stats_kernel<<<1, 256>>>();
    tile_kernel<<<NTILES, THREADS, SM_BYTES>>>(node_repr, edge_repr, p);
    finalize_stats_kernel<<<1, 256>>>();
    const int total4 = N_NODES * OUT / 4;
    norm_relu_kernel<<<(total4 + 255) / 256, 256>>>(out);
}

// round 5
// speedup vs baseline: 7.5676x; 1.1732x over previous
#include <cuda_runtime.h>
#include <cuda_fp16.h>

#define N_NODES   200000
#define N_EDGES   600000
#define NODE_SIZE 256
#define EDGE_SIZE 64
#define OUT       256
#define KTOT      576
#define BUCKET    40000
#define NDEG      5
#define CHUNKS    9                 // 9 x 64-k chunks
#define TILES_PB  313               // ceil(40000/128)
#define NTILES    (NDEG * TILES_PB) // 1565
#define THREADS   512

// ---- device scratch --------------------------------------------------------
__device__ float          g_acts[(size_t)N_NODES * OUT];
__device__ float          g_sum[OUT];
__device__ float          g_sq[OUT];
__device__ float          g_scale[OUT];
__device__ float          g_shift[OUT];
// pre-swizzled fp16 weights: [bucket*9+chunk] blobs of 256 rows x 128B
__device__ unsigned short g_B[45 * 16384];

// ---- SMEM layout (dynamic) ---------------------------------------------------
#define SM_BUF    49152
#define SM_BOFF   16384
#define SM_NN     98304
#define SM_EN     100864
#define SM_SUM    103424
#define SM_SQ     104448
#define SM_BYTES  105472

static __device__ __forceinline__ void mma16816(float* d, const unsigned* a,
                                                const unsigned* b) {
    asm volatile(
        "mma.sync.aligned.m16n8k16.row.col.f32.f16.f16.f32 "
        "{%0,%1,%2,%3}, {%4,%5,%6,%7}, {%8,%9}, {%0,%1,%2,%3};"
        : "+f"(d[0]), "+f"(d[1]), "+f"(d[2]), "+f"(d[3])
        : "r"(a[0]), "r"(a[1]), "r"(a[2]), "r"(a[3]), "r"(b[0]), "r"(b[1]));
}

static __device__ __forceinline__ void ldm4(unsigned& r0, unsigned& r1,
                                            unsigned& r2, unsigned& r3,
                                            unsigned addr) {
    asm volatile("ldmatrix.sync.aligned.m8n8.x4.shared.b16 {%0,%1,%2,%3}, [%4];"
                 : "=r"(r0), "=r"(r1), "=r"(r2), "=r"(r3) : "r"(addr));
}

#define CP_ASYNC16(dst, src) \
    asm volatile("cp.async.cg.shared.global [%0], [%1], 16;" :: "r"(dst), "l"(src))
#define CP_COMMIT()  asm volatile("cp.async.commit_group;" ::: "memory")
#define CP_WAIT0()   asm volatile("cp.async.wait_group 0;"  ::: "memory")

// ---- kernel 0: build pre-swizzled fp16 weight blobs --------------------------
// blob(bucket,c): element (n,k) at half-index n*64 + ((k>>3)^(n&7))*8 + (k&7)
__global__ void build_b_kernel(const float* __restrict__ W_self,
                               const float* __restrict__ W_deg) {
    const int bc = blockIdx.x;              // bucket*9 + chunk
    const int d = bc / CHUNKS, c = bc - d * CHUNKS;
    const int n = threadIdx.x;              // 0..255
    unsigned short* blob = g_B + (size_t)bc * 16384 + n * 64;
    const unsigned sx = n & 7;
    for (int k = 0; k < 64; ++k) {
        const int kg = c * 64 + k;
        float w;
        if (kg < NODE_SIZE)
            w = W_self[n * NODE_SIZE + kg];
        else
            w = W_deg[((size_t)(d * OUT + n)) * (NODE_SIZE + EDGE_SIZE) + (kg - NODE_SIZE)];
        blob[(((unsigned)(k >> 3)) ^ sx) * 8 + (k & 7)] = __half_as_ushort(__float2half_rn(w));
    }
}

// ---- kernel 1: zero stats -----------------------------------------------------
__global__ void zero_stats_kernel() {
    int t = threadIdx.x;
    if (t < OUT) { g_sum[t] = 0.f; g_sq[t] = 0.f; }
}

// ---- kernel 2: fused gather + HMMA GEMM + stats -------------------------------
struct NbrPtrs { const int* nn[NDEG]; const int* en[NDEG]; };

static __device__ __forceinline__ void gatherA(
    int cc, int row, int q, bool live, int row0, int deg,
    const float* __restrict__ node_repr, const float* __restrict__ edge_repr,
    const int* s_nn, const int* s_en, float4* s) {
    s[0] = s[1] = s[2] = s[3] = make_float4(0.f, 0.f, 0.f, 0.f);
    if (!live) return;
    if (cc < 4) {
        const float4* p = (const float4*)(node_repr + (size_t)(row0 + row) * NODE_SIZE + cc * 64 + q * 16);
        #pragma unroll
        for (int i = 0; i < 4; ++i) s[i] = p[i];
    } else if (cc < 8) {
        const int kk = (cc - 4) * 64 + q * 16;
        for (int j = 0; j < deg; ++j) {
            const float4* p = (const float4*)(node_repr + (size_t)s_nn[row * NDEG + j] * NODE_SIZE + kk);
            #pragma unroll
            for (int i = 0; i < 4; ++i) {
                float4 w = p[i];
                s[i].x += w.x; s[i].y += w.y; s[i].z += w.z; s[i].w += w.w;
            }
        }
    } else {
        for (int j = 0; j < deg; ++j) {
            const float4* p = (const float4*)(edge_repr + (size_t)s_en[row * NDEG + j] * EDGE_SIZE + q * 16);
            #pragma unroll
            for (int i = 0; i < 4; ++i) {
                float4 w = p[i];
                s[i].x += w.x; s[i].y += w.y; s[i].z += w.z; s[i].w += w.w;
            }
        }
    }
}

// convert 16 fp32 -> fp16 and store 2x16B into swizzled A tile (byte offsets in smem)
static __device__ __forceinline__ void cvtStsA(char* bufA, int row, int q, const float4* s) {
    unsigned h[8];
    #pragma unroll
    for (int i = 0; i < 4; ++i) {
        __half2 p0 = __floats2half2_rn(((const float*)&s[i])[0], ((const float*)&s[i])[1]);
        __half2 p1 = __floats2half2_rn(((const float*)&s[i])[2], ((const float*)&s[i])[3]);
        h[2 * i]     = *(unsigned*)&p0;
        h[2 * i + 1] = *(unsigned*)&p1;
    }
    const unsigned sx = row & 7;
    unsigned off0 = row * 128 + ((((unsigned)(q * 2))     ^ sx) << 4);
    unsigned off1 = row * 128 + ((((unsigned)(q * 2 + 1)) ^ sx) << 4);
    *(uint4*)(bufA + off0) = make_uint4(h[0], h[1], h[2], h[3]);
    *(uint4*)(bufA + off1) = make_uint4(h[4], h[5], h[6], h[7]);
}

// issue 4x cp.async of 16B for the B blob into smem buffer
static __device__ __forceinline__ void cpB(unsigned bufB_sa, int bucket, int cc, int tid) {
    const char* src = (const char*)(g_B + (size_t)(bucket * CHUNKS + cc) * 16384);
    #pragma unroll
    for (int i = 0; i < 4; ++i)
        CP_ASYNC16(bufB_sa + (tid + i * 512) * 16, src + (tid + i * 512) * 16);
    CP_COMMIT();
}

__global__ __launch_bounds__(THREADS, 1)
void tile_kernel(const float* __restrict__ node_repr,
                 const float* __restrict__ edge_repr,
                 NbrPtrs p) {
    extern __shared__ char smem[];
    const unsigned smem_sa = (unsigned)__cvta_generic_to_shared(smem);
    const int tid    = threadIdx.x;
    const int bid    = blockIdx.x;
    const int bucket = bid / TILES_PB;
    const int tile   = bid - bucket * TILES_PB;
    const int deg    = bucket + 1;
    const int li0    = tile * 128;
    const int row0   = bucket * BUCKET + li0;
    const int valid  = (BUCKET - li0) < 128 ? (BUCKET - li0) : 128;

    int* s_nn = (int*)(smem + SM_NN);
    int* s_en = (int*)(smem + SM_EN);
    float* s_sum = (float*)(smem + SM_SUM);
    float* s_sq  = (float*)(smem + SM_SQ);

    if (tid < 256) { s_sum[tid] = 0.f; s_sq[tid] = 0.f; }

    {   // neighbor indices
        const int* nn = p.nn[bucket];
        const int* en = p.en[bucket];
        for (int i = tid; i < valid * deg; i += THREADS) {
            int r = i / deg, j = i - r * deg;
            s_nn[r * NDEG + j] = nn[(li0 + r) * deg + j];
            s_en[r * NDEG + j] = en[(li0 + r) * deg + j];
        }
    }
    __syncthreads();

    const int row = tid >> 2;          // staging row 0..127
    const int q   = tid & 3;           // staging k-quad
    const bool live = row < valid;

    // stage chunk 0 into buf 0
    {
        float4 ar[4];
        cpB(smem_sa + SM_BOFF, bucket, 0, tid);
        gatherA(0, row, q, live, row0, deg, node_repr, edge_repr, s_nn, s_en, ar);
        cvtStsA(smem, row, q, ar);
        CP_WAIT0();
    }
    __syncthreads();

    // warp/lane geometry
    const int wid  = tid >> 5, lane = tid & 31;
    const int wr   = wid & 3,  wc   = wid >> 2;
    // ldmatrix A: lanes 0-7 -> rows 0-7 (k-half 0), 8-15 -> rows 8-15 (kh 0),
    //             16-23 -> rows 0-7 (kh 1), 24-31 -> rows 8-15 (kh 1)
    const int rowA   = wr * 32 + (lane & 7) + ((lane >> 3) & 1) * 8;
    const unsigned khA = (unsigned)(lane >> 4);          // 0/1 -> k 16B-chunk offset
    const unsigned sxA = (unsigned)(rowA & 7);
    // ldmatrix B: lanes 0-7 -> n 0-7 (kh 0), 8-15 -> n 0-7 (kh 1),
    //             16-23 -> n 8-15 (kh 0), 24-31 -> n 8-15 (kh 1)
    const unsigned khB = (unsigned)((lane >> 3) & 1);
    const int nBoff  = ((lane >> 4) ? 8 : 0) + (lane & 7);

    float acc[2][8][4];
    #pragma unroll
    for (int mt = 0; mt < 2; ++mt)
        #pragma unroll
        for (int nt = 0; nt < 8; ++nt)
            #pragma unroll
            for (int i = 0; i < 4; ++i) acc[mt][nt][i] = 0.f;

    for (int c = 0; c < CHUNKS; ++c) {
        const int nxt = c + 1;
        float4 ar[4];
        if (nxt < CHUNKS) {   // prefetch next chunk
            cpB(smem_sa + (nxt & 1) * SM_BUF + SM_BOFF, bucket, nxt, tid);
            gatherA(nxt, row, q, live, row0, deg, node_repr, edge_repr, s_nn, s_en, ar);
        }

        // ---- MMA on buffer c&1 ----
        {
            const unsigned bufA_sa = smem_sa + (c & 1) * SM_BUF;
            const unsigned bufB_sa = bufA_sa + SM_BOFF;
            #pragma unroll
            for (int ks = 0; ks < 4; ++ks) {
                const unsigned c0 = 2 * ks;
                unsigned a[2][4];
                #pragma unroll
                for (int mt = 0; mt < 2; ++mt) {
                    const unsigned addr = bufA_sa + (unsigned)(rowA + mt * 16) * 128
                                        + (((c0 + khA) ^ sxA) << 4);
                    ldm4(a[mt][0], a[mt][1], a[mt][2], a[mt][3], addr);
                }
                unsigned b[8][2];
                #pragma unroll
                for (int pr = 0; pr < 4; ++pr) {
                    const int nrow = wc * 64 + pr * 16 + nBoff;
                    const unsigned addr = bufB_sa + (unsigned)nrow * 128
                                        + (((c0 + khB) ^ (unsigned)(nrow & 7)) << 4);
                    ldm4(b[2 * pr][0], b[2 * pr][1], b[2 * pr + 1][0], b[2 * pr + 1][1], addr);
                }
                #pragma unroll
                for (int mt = 0; mt < 2; ++mt)
                    #pragma unroll
                    for (int nt = 0; nt < 8; ++nt)
                        mma16816(acc[mt][nt], a[mt], b[nt]);
            }
        }

        if (nxt < CHUNKS) {   // commit next A chunk to other buffer
            cvtStsA(smem + (nxt & 1) * SM_BUF, row, q, ar);
        }
        CP_WAIT0();
        __syncthreads();
    }

    // ---- epilogue: store acts, per-column stats ----
    {
        #pragma unroll
        for (int mt = 0; mt < 2; ++mt) {
            const int r0 = wr * 32 + mt * 16 + (lane >> 2);
            #pragma unroll
            for (int nt = 0; nt < 8; ++nt) {
                const int n0 = wc * 64 + nt * 8 + (lane & 3) * 2;
                if (r0 < valid)
                    *(float2*)(g_acts + (size_t)(row0 + r0) * OUT + n0) =
                        make_float2(acc[mt][nt][0], acc[mt][nt][1]);
                if (r0 + 8 < valid)
                    *(float2*)(g_acts + (size_t)(row0 + r0 + 8) * OUT + n0) =
                        make_float2(acc[mt][nt][2], acc[mt][nt][3]);
            }
        }
        #pragma unroll
        for (int nt = 0; nt < 8; ++nt) {
            #pragma unroll
            for (int h = 0; h < 2; ++h) {
                float s = acc[0][nt][h] + acc[0][nt][2 + h] +
                          acc[1][nt][h] + acc[1][nt][2 + h];
                float qq = acc[0][nt][h] * acc[0][nt][h] + acc[0][nt][2 + h] * acc[0][nt][2 + h] +
                           acc[1][nt][h] * acc[1][nt][h] + acc[1][nt][2 + h] * acc[1][nt][2 + h];
                #pragma unroll
                for (int d = 4; d < 32; d <<= 1) {
                    s  += __shfl_xor_sync(0xffffffffu, s, d);
                    qq += __shfl_xor_sync(0xffffffffu, qq, d);
                }
                if (lane < 4) {
                    const int col = wc * 64 + nt * 8 + lane * 2 + h;
                    atomicAdd(&s_sum[col], s);
                    atomicAdd(&s_sq[col], qq);
                }
            }
        }
    }
    __syncthreads();
    if (tid < 256) {
        atomicAdd(&g_sum[tid], s_sum[tid]);
        atomicAdd(&g_sq[tid],  s_sq[tid]);
    }
}

// ---- kernel 3: finalize BN stats ----------------------------------------------
__global__ void finalize_stats_kernel() {
    int c = threadIdx.x;
    float m   = g_sum[c] * (1.0f / N_NODES);
    float var = g_sq[c] * (1.0f / N_NODES) - m * m;
    float inv = rsqrtf(var + 1e-5f);
    g_scale[c] = inv;
    g_shift[c] = -m * inv;
}

// ---- kernel 4: normalize + relu --------------------------------------------------
__global__ __launch_bounds__(256)
void norm_relu_kernel(float* __restrict__ out) {
    const size_t idx = (size_t)blockIdx.x * blockDim.x + threadIdx.x;
    const size_t total4 = (size_t)N_NODES * OUT / 4;
    if (idx >= total4) return;
    const int c4 = (int)(idx & (OUT / 4 - 1));
    const float4 v  = ((const float4*)g_acts)[idx];
    const float4 sc = ((const float4*)g_scale)[c4];
    const float4 sh = ((const float4*)g_shift)[c4];
    float4 r;
    r.x = fmaxf(0.f, v.x * sc.x + sh.x);
    r.y = fmaxf(0.f, v.y * sc.y + sh.y);
    r.z = fmaxf(0.f, v.z * sc.z + sh.z);
    r.w = fmaxf(0.f, v.w * sc.w + sh.w);
    ((float4*)out)[idx] = r;
}

// ---- launch -----------------------------------------------------------------------
extern "C" void kernel_launch(void* const* d_in, const int* in_sizes, int n_in,
                              void* d_out, int out_size) {
    const float* node_repr = (const float*)d_in[0];
    const float* edge_repr = (const float*)d_in[1];
    NbrPtrs p;
    // inputs interleaved: d_in[2]=node_nbr_1, d_in[3]=edge_nbr_1, ...
    for (int d = 0; d < NDEG; ++d) {
        p.nn[d] = (const int*)d_in[2 + 2 * d];
        p.en[d] = (const int*)d_in[3 + 2 * d];
    }
    const float* W_self = (const float*)d_in[12];
    const float* W_deg  = (const float*)d_in[13];
    float* out = (float*)d_out;

    static bool attr_done = false;
    if (!attr_done) {
        cudaFuncSetAttribute(tile_kernel, cudaFuncAttributeMaxDynamicSharedMemorySize, SM_BYTES);
        attr_done = true;
    }

    build_b_kernel<<<NDEG * CHUNKS, 256>>>(W_self, W_deg);
    zero_stats_kernel<<<1, 256>>>();
    zero_stats_kernel<<<1, 256>>>();   // dummy: places tile_kernel at the launch
                                       // index ncu samples (4th), for profiling
    tile_kernel<<<NTILES, THREADS, SM_BYTES>>>(node_repr, edge_repr, p);
    finalize_stats_kernel<<<1, 256>>>();
    const int total4 = N_NODES * OUT / 4;
    norm_relu_kernel<<<(total4 + 255) / 256, 256>>>(out);
}

// round 6
// speedup vs baseline: 8.4495x; 1.1165x over previous
#include <cuda_runtime.h>
#include <cuda_fp16.h>

#define N_NODES   200000
#define N_EDGES   600000
#define NODE_SIZE 256
#define EDGE_SIZE 64
#define OUT       256
#define KTOT      576
#define BUCKET    40000
#define NDEG      5
#define CHUNKS    9                 // 9 x 64-k chunks
#define TILES_PB  625               // 40000 / 64, exact
#define NTILES    (NDEG * TILES_PB) // 3125
#define THREADS   256

// ---- device scratch --------------------------------------------------------
__device__ __half         g_acts[(size_t)N_NODES * OUT];
__device__ float          g_sum[OUT];
__device__ float          g_sq[OUT];
__device__ float          g_scale[OUT];
__device__ float          g_shift[OUT];
// pre-swizzled fp16 weights: [bucket*9+chunk] blobs of 256 rows x 128B
__device__ unsigned short g_B[45 * 16384];

// ---- SMEM layout (dynamic) ---------------------------------------------------
// stage s at s*40960: A 64x128B (8192) ; B 256x128B at +8192 (32768)
#define SM_BUF    40960
#define SM_BOFF   8192
#define SM_NN     81920
#define SM_EN     83200
#define SM_SUM    84480
#define SM_SQ     85504
#define SM_BYTES  86528

static __device__ __forceinline__ void mma16816(float* d, const unsigned* a,
                                                const unsigned* b) {
    asm volatile(
        "mma.sync.aligned.m16n8k16.row.col.f32.f16.f16.f32 "
        "{%0,%1,%2,%3}, {%4,%5,%6,%7}, {%8,%9}, {%0,%1,%2,%3};"
        : "+f"(d[0]), "+f"(d[1]), "+f"(d[2]), "+f"(d[3])
        : "r"(a[0]), "r"(a[1]), "r"(a[2]), "r"(a[3]), "r"(b[0]), "r"(b[1]));
}

static __device__ __forceinline__ void ldm4(unsigned& r0, unsigned& r1,
                                            unsigned& r2, unsigned& r3,
                                            unsigned addr) {
    asm volatile("ldmatrix.sync.aligned.m8n8.x4.shared.b16 {%0,%1,%2,%3}, [%4];"
                 : "=r"(r0), "=r"(r1), "=r"(r2), "=r"(r3) : "r"(addr));
}

#define CP_ASYNC16(dst, src) \
    asm volatile("cp.async.cg.shared.global [%0], [%1], 16;" :: "r"(dst), "l"(src))
#define CP_COMMIT()  asm volatile("cp.async.commit_group;" ::: "memory")
#define CP_WAIT0()   asm volatile("cp.async.wait_group 0;"  ::: "memory")

// ---- kernel 0: build pre-swizzled fp16 weight blobs --------------------------
// blob(bucket,c): element (n,k) at half-index n*64 + ((k>>3)^(n&7))*8 + (k&7)
__global__ void build_b_kernel(const float* __restrict__ W_self,
                               const float* __restrict__ W_deg) {
    const int bc = blockIdx.x;              // bucket*9 + chunk
    const int d = bc / CHUNKS, c = bc - d * CHUNKS;
    const int n = threadIdx.x;              // 0..255
    unsigned short* blob = g_B + (size_t)bc * 16384 + n * 64;
    const unsigned sx = n & 7;
    for (int k = 0; k < 64; ++k) {
        const int kg = c * 64 + k;
        float w;
        if (kg < NODE_SIZE)
            w = W_self[n * NODE_SIZE + kg];
        else
            w = W_deg[((size_t)(d * OUT + n)) * (NODE_SIZE + EDGE_SIZE) + (kg - NODE_SIZE)];
        blob[(((unsigned)(k >> 3)) ^ sx) * 8 + (k & 7)] = __half_as_ushort(__float2half_rn(w));
    }
}

// ---- kernel 1: zero stats -----------------------------------------------------
__global__ void zero_stats_kernel() {
    int t = threadIdx.x;
    if (t < OUT) { g_sum[t] = 0.f; g_sq[t] = 0.f; }
}

// ---- kernel 2: fused gather + HMMA GEMM + stats -------------------------------
struct NbrPtrs { const int* nn[NDEG]; const int* en[NDEG]; };

static __device__ __forceinline__ void gatherA(
    int cc, int row, int q, int row0, int deg,
    const float* __restrict__ node_repr, const float* __restrict__ edge_repr,
    const int* s_nn, const int* s_en, float4* s) {
    if (cc < 4) {
        const float4* p = (const float4*)(node_repr + (size_t)(row0 + row) * NODE_SIZE + cc * 64 + q * 16);
        #pragma unroll
        for (int i = 0; i < 4; ++i) s[i] = p[i];
    } else if (cc < 8) {
        s[0] = s[1] = s[2] = s[3] = make_float4(0.f, 0.f, 0.f, 0.f);
        const int kk = (cc - 4) * 64 + q * 16;
        for (int j = 0; j < deg; ++j) {
            const float4* p = (const float4*)(node_repr + (size_t)s_nn[row * NDEG + j] * NODE_SIZE + kk);
            #pragma unroll
            for (int i = 0; i < 4; ++i) {
                float4 w = p[i];
                s[i].x += w.x; s[i].y += w.y; s[i].z += w.z; s[i].w += w.w;
            }
        }
    } else {
        s[0] = s[1] = s[2] = s[3] = make_float4(0.f, 0.f, 0.f, 0.f);
        for (int j = 0; j < deg; ++j) {
            const float4* p = (const float4*)(edge_repr + (size_t)s_en[row * NDEG + j] * EDGE_SIZE + q * 16);
            #pragma unroll
            for (int i = 0; i < 4; ++i) {
                float4 w = p[i];
                s[i].x += w.x; s[i].y += w.y; s[i].z += w.z; s[i].w += w.w;
            }
        }
    }
}

// convert 16 fp32 -> fp16 and store 2x16B into swizzled A tile
static __device__ __forceinline__ void cvtStsA(char* bufA, int row, int q, const float4* s) {
    unsigned h[8];
    #pragma unroll
    for (int i = 0; i < 4; ++i) {
        __half2 p0 = __floats2half2_rn(((const float*)&s[i])[0], ((const float*)&s[i])[1]);
        __half2 p1 = __floats2half2_rn(((const float*)&s[i])[2], ((const float*)&s[i])[3]);
        h[2 * i]     = *(unsigned*)&p0;
        h[2 * i + 1] = *(unsigned*)&p1;
    }
    const unsigned sx = row & 7;
    unsigned off0 = row * 128 + ((((unsigned)(q * 2))     ^ sx) << 4);
    unsigned off1 = row * 128 + ((((unsigned)(q * 2 + 1)) ^ sx) << 4);
    *(uint4*)(bufA + off0) = make_uint4(h[0], h[1], h[2], h[3]);
    *(uint4*)(bufA + off1) = make_uint4(h[4], h[5], h[6], h[7]);
}

// issue 8x cp.async of 16B for the full 32KB B blob into smem buffer
static __device__ __forceinline__ void cpB(unsigned bufB_sa, int bucket, int cc, int tid) {
    const char* src = (const char*)(g_B + (size_t)(bucket * CHUNKS + cc) * 16384);
    #pragma unroll
    for (int i = 0; i < 8; ++i)
        CP_ASYNC16(bufB_sa + (tid + i * 256) * 16, src + (tid + i * 256) * 16);
    CP_COMMIT();
}

__global__ __launch_bounds__(THREADS, 2)
void tile_kernel(const float* __restrict__ node_repr,
                 const float* __restrict__ edge_repr,
                 NbrPtrs p) {
    extern __shared__ char smem[];
    const unsigned smem_sa = (unsigned)__cvta_generic_to_shared(smem);
    const int tid    = threadIdx.x;
    const int bid    = blockIdx.x;
    const int bucket = bid / TILES_PB;
    const int tile   = bid - bucket * TILES_PB;
    const int deg    = bucket + 1;
    const int li0    = tile * 64;
    const int row0   = bucket * BUCKET + li0;

    int* s_nn = (int*)(smem + SM_NN);
    int* s_en = (int*)(smem + SM_EN);
    float* s_sum = (float*)(smem + SM_SUM);
    float* s_sq  = (float*)(smem + SM_SQ);

    s_sum[tid] = 0.f; s_sq[tid] = 0.f;

    {   // neighbor indices (64 rows, all valid)
        const int* nn = p.nn[bucket];
        const int* en = p.en[bucket];
        for (int i = tid; i < 64 * deg; i += THREADS) {
            int r = i / deg, j = i - r * deg;
            s_nn[r * NDEG + j] = nn[(li0 + r) * deg + j];
            s_en[r * NDEG + j] = en[(li0 + r) * deg + j];
        }
    }
    __syncthreads();

    const int row = tid >> 2;          // staging row 0..63
    const int q   = tid & 3;           // staging k-quad

    // stage chunk 0 into buf 0
    {
        float4 ar[4];
        cpB(smem_sa + SM_BOFF, bucket, 0, tid);
        gatherA(0, row, q, row0, deg, node_repr, edge_repr, s_nn, s_en, ar);
        cvtStsA(smem, row, q, ar);
        CP_WAIT0();
    }
    __syncthreads();

    // warp/lane geometry: 2 m-warps x 4 n-warps
    const int wid  = tid >> 5, lane = tid & 31;
    const int wr   = wid & 1,  wc   = wid >> 1;
    const int rowA   = wr * 32 + (lane & 7) + ((lane >> 3) & 1) * 8;
    const unsigned khA = (unsigned)(lane >> 4);
    const unsigned sxA = (unsigned)(rowA & 7);
    const unsigned khB = (unsigned)((lane >> 3) & 1);
    const int nBoff  = ((lane >> 4) ? 8 : 0) + (lane & 7);

    float acc[2][8][4];
    #pragma unroll
    for (int mt = 0; mt < 2; ++mt)
        #pragma unroll
        for (int nt = 0; nt < 8; ++nt)
            #pragma unroll
            for (int i = 0; i < 4; ++i) acc[mt][nt][i] = 0.f;

    for (int c = 0; c < CHUNKS; ++c) {
        const int nxt = c + 1;
        float4 ar[4];
        if (nxt < CHUNKS) {   // prefetch next chunk
            cpB(smem_sa + (nxt & 1) * SM_BUF + SM_BOFF, bucket, nxt, tid);
            gatherA(nxt, row, q, row0, deg, node_repr, edge_repr, s_nn, s_en, ar);
        }

        // ---- MMA on buffer c&1 ----
        {
            const unsigned bufA_sa = smem_sa + (c & 1) * SM_BUF;
            const unsigned bufB_sa = bufA_sa + SM_BOFF;
            #pragma unroll
            for (int ks = 0; ks < 4; ++ks) {
                const unsigned c0 = 2 * ks;
                unsigned a[2][4];
                #pragma unroll
                for (int mt = 0; mt < 2; ++mt) {
                    const unsigned addr = bufA_sa + (unsigned)(rowA + mt * 16) * 128
                                        + (((c0 + khA) ^ sxA) << 4);
                    ldm4(a[mt][0], a[mt][1], a[mt][2], a[mt][3], addr);
                }
                unsigned b[8][2];
                #pragma unroll
                for (int pr = 0; pr < 4; ++pr) {
                    const int nrow = wc * 64 + pr * 16 + nBoff;
                    const unsigned addr = bufB_sa + (unsigned)nrow * 128
                                        + (((c0 + khB) ^ (unsigned)(nrow & 7)) << 4);
                    ldm4(b[2 * pr][0], b[2 * pr][1], b[2 * pr + 1][0], b[2 * pr + 1][1], addr);
                }
                #pragma unroll
                for (int mt = 0; mt < 2; ++mt)
                    #pragma unroll
                    for (int nt = 0; nt < 8; ++nt)
                        mma16816(acc[mt][nt], a[mt], b[nt]);
            }
        }

        if (nxt < CHUNKS) {
            cvtStsA(smem + (nxt & 1) * SM_BUF, row, q, ar);
        }
        CP_WAIT0();
        __syncthreads();
    }

    // ---- epilogue: store acts (fp16), per-column stats ----
    {
        #pragma unroll
        for (int mt = 0; mt < 2; ++mt) {
            const int r0 = wr * 32 + mt * 16 + (lane >> 2);
            #pragma unroll
            for (int nt = 0; nt < 8; ++nt) {
                const int n0 = wc * 64 + nt * 8 + (lane & 3) * 2;
                __half2 h0 = __floats2half2_rn(acc[mt][nt][0], acc[mt][nt][1]);
                __half2 h1 = __floats2half2_rn(acc[mt][nt][2], acc[mt][nt][3]);
                *(__half2*)(g_acts + (size_t)(row0 + r0) * OUT + n0) = h0;
                *(__half2*)(g_acts + (size_t)(row0 + r0 + 8) * OUT + n0) = h1;
            }
        }
        #pragma unroll
        for (int nt = 0; nt < 8; ++nt) {
            #pragma unroll
            for (int h = 0; h < 2; ++h) {
                float s = acc[0][nt][h] + acc[0][nt][2 + h] +
                          acc[1][nt][h] + acc[1][nt][2 + h];
                float qq = acc[0][nt][h] * acc[0][nt][h] + acc[0][nt][2 + h] * acc[0][nt][2 + h] +
                           acc[1][nt][h] * acc[1][nt][h] + acc[1][nt][2 + h] * acc[1][nt][2 + h];
                #pragma unroll
                for (int d = 4; d < 32; d <<= 1) {
                    s  += __shfl_xor_sync(0xffffffffu, s, d);
                    qq += __shfl_xor_sync(0xffffffffu, qq, d);
                }
                if (lane < 4) {
                    const int col = wc * 64 + nt * 8 + lane * 2 + h;
                    atomicAdd(&s_sum[col], s);
                    atomicAdd(&s_sq[col], qq);
                }
            }
        }
    }
    __syncthreads();
    atomicAdd(&g_sum[tid], s_sum[tid]);
    atomicAdd(&g_sq[tid],  s_sq[tid]);
}

// ---- kernel 3: finalize BN stats ----------------------------------------------
__global__ void finalize_stats_kernel() {
    int c = threadIdx.x;
    float m   = g_sum[c] * (1.0f / N_NODES);
    float var = g_sq[c] * (1.0f / N_NODES) - m * m;
    float inv = rsqrtf(var + 1e-5f);
    g_scale[c] = inv;
    g_shift[c] = -m * inv;
}

// ---- kernel 4: normalize + relu --------------------------------------------------
// reads fp16 acts (8 at a time), writes fp32 out
__global__ __launch_bounds__(256)
void norm_relu_kernel(float* __restrict__ out) {
    const size_t idx = (size_t)blockIdx.x * blockDim.x + threadIdx.x;  // uint4 = 8 halves
    const size_t total8 = (size_t)N_NODES * OUT / 8;
    if (idx >= total8) return;
    const int c8 = (int)(idx & (OUT / 8 - 1));
    const uint4 raw = ((const uint4*)g_acts)[idx];
    const unsigned* rw = (const unsigned*)&raw;
    float4 o[2];
    #pragma unroll
    for (int i = 0; i < 2; ++i) {
        const float4 sc = ((const float4*)g_scale)[c8 * 2 + i];
        const float4 sh = ((const float4*)g_shift)[c8 * 2 + i];
        float2 v0 = __half22float2(*(const __half2*)&rw[i * 2 + 0]);
        float2 v1 = __half22float2(*(const __half2*)&rw[i * 2 + 1]);
        o[i].x = fmaxf(0.f, v0.x * sc.x + sh.x);
        o[i].y = fmaxf(0.f, v0.y * sc.y + sh.y);
        o[i].z = fmaxf(0.f, v1.x * sc.z + sh.z);
        o[i].w = fmaxf(0.f, v1.y * sc.w + sh.w);
    }
    ((float4*)out)[idx * 2]     = o[0];
    ((float4*)out)[idx * 2 + 1] = o[1];
}

// ---- launch -----------------------------------------------------------------------
extern "C" void kernel_launch(void* const* d_in, const int* in_sizes, int n_in,
                              void* d_out, int out_size) {
    const float* node_repr = (const float*)d_in[0];
    const float* edge_repr = (const float*)d_in[1];
    NbrPtrs p;
    // inputs interleaved: d_in[2]=node_nbr_1, d_in[3]=edge_nbr_1, ...
    for (int d = 0; d < NDEG; ++d) {
        p.nn[d] = (const int*)d_in[2 + 2 * d];
        p.en[d] = (const int*)d_in[3 + 2 * d];
    }
    const float* W_self = (const float*)d_in[12];
    const float* W_deg  = (const float*)d_in[13];
    float* out = (float*)d_out;

    static bool attr_done = false;
    if (!attr_done) {
        cudaFuncSetAttribute(tile_kernel, cudaFuncAttributeMaxDynamicSharedMemorySize, SM_BYTES);
        attr_done = true;
    }

    build_b_kernel<<<NDEG * CHUNKS, 256>>>(W_self, W_deg);
    zero_stats_kernel<<<1, 256>>>();
    zero_stats_kernel<<<1, 256>>>();   // dummy: keeps tile_kernel at the launch
                                       // index ncu samples (4th)
    tile_kernel<<<NTILES, THREADS, SM_BYTES>>>(node_repr, edge_repr, p);
    finalize_stats_kernel<<<1, 256>>>();
    const int total8 = N_NODES * OUT / 8;
    norm_relu_kernel<<<(total8 + 255) / 256, 256>>>(out);
}